// round 14
// baseline (speedup 1.0000x reference)
#include <cuda_runtime.h>
#include <cuda_bf16.h>
#include <stdint.h>

#define D_DIM 3072
#define NB    4096
#define BM    128
#define BN    128
#define KC    64
#define NCHUNK (D_DIM / KC)        // 48 chunks (single bf16 pass)
#define STAGES 3
#define PITCH  144                 // bytes per smem row (64 bf16 = 128B + 16B pad)
#define ATILE  (BM * PITCH)        // 18432 bytes
#define STAGE_BYTES (2 * ATILE)    // A + B = 36864
#define SMEM_TOTAL (STAGES * STAGE_BYTES)   // 110592 (2 CTAs/SM: 216KB <= 228KB)
#define MARGIN 48.0f               // >> 2*max|vhat-v|; validated R7/R9/R11/R12
#define CAP    512                 // per-row candidate slots
#define QCAP   (NB * 64)           // global queue capacity

// ---------------- scratch (no cudaMalloc allowed) ----------------
__device__ float g_x2[NB];
__device__ float g_y2[NB];
__device__ unsigned long long g_best[NB];    // approx: (vhat bits << 32) | col
__device__ unsigned long long g_fbest[NB];   // refined: (v bits << 32) | col
__device__ int g_cnt[NB];
__device__ int g_qcnt;
__device__ unsigned long long g_cand[(size_t)NB * CAP];
__device__ unsigned g_q[QCAP];               // packed (row << 12) | col
__device__ __nv_bfloat16 g_xb[(size_t)NB * D_DIM];
__device__ __nv_bfloat16 g_yb[(size_t)NB * D_DIM];

// ---------------- PTX helpers ----------------
__device__ __forceinline__ uint32_t smem_u32(const void* p) {
    uint32_t a;
    asm("{ .reg .u64 t; cvta.to.shared.u64 t, %1; cvt.u32.u64 %0, t; }" : "=r"(a) : "l"(p));
    return a;
}
__device__ __forceinline__ void cp_async16(uint32_t s, const void* g) {
    asm volatile("cp.async.cg.shared.global [%0], [%1], 16;\n" :: "r"(s), "l"(g) : "memory");
}
__device__ __forceinline__ void ldsm_x4(uint32_t& r0, uint32_t& r1, uint32_t& r2, uint32_t& r3,
                                        uint32_t addr) {
    asm volatile("ldmatrix.sync.aligned.m8n8.x4.shared.b16 {%0,%1,%2,%3}, [%4];"
                 : "=r"(r0), "=r"(r1), "=r"(r2), "=r"(r3) : "r"(addr));
}
__device__ __forceinline__ void mma16816(float* d, const uint32_t* a, const uint32_t* b) {
    asm volatile(
        "mma.sync.aligned.m16n8k16.row.col.f32.bf16.bf16.f32 "
        "{%0,%1,%2,%3}, {%4,%5,%6,%7}, {%8,%9}, {%0,%1,%2,%3};"
        : "+f"(d[0]), "+f"(d[1]), "+f"(d[2]), "+f"(d[3])
        : "r"(a[0]), "r"(a[1]), "r"(a[2]), "r"(a[3]), "r"(b[0]), "r"(b[1]));
}

// ---------------- fused fp32->bf16 conversion + row squared-norms ----------------
__global__ void convert_norms_kernel(const float* __restrict__ x, const float* __restrict__ y) {
    const int row = blockIdx.x;
    const bool isY = row >= NB;
    const int r = isY ? row - NB : row;
    const float* src = (isY ? y : x) + (size_t)r * D_DIM;
    __nv_bfloat16* dst = (isY ? g_yb : g_xb) + (size_t)r * D_DIM;

    float s = 0.f;
    #pragma unroll 3
    for (int k = threadIdx.x * 4; k < D_DIM; k += 256 * 4) {
        float4 v = *(const float4*)(src + k);
        s += v.x * v.x + v.y * v.y + v.z * v.z + v.w * v.w;
        __nv_bfloat162 p0 = __halves2bfloat162(__float2bfloat16(v.x), __float2bfloat16(v.y));
        __nv_bfloat162 p1 = __halves2bfloat162(__float2bfloat16(v.z), __float2bfloat16(v.w));
        ((__nv_bfloat162*)(dst + k))[0] = p0;
        ((__nv_bfloat162*)(dst + k))[1] = p1;
    }
    __shared__ float sm[256];
    sm[threadIdx.x] = s;
    __syncthreads();
    for (int o = 128; o > 0; o >>= 1) {
        if (threadIdx.x < o) sm[threadIdx.x] += sm[threadIdx.x + o];
        __syncthreads();
    }
    if (threadIdx.x == 0) {
        if (isY) g_y2[r] = sm[0];
        else     g_x2[r] = sm[0];
    }
}

// ---------------- passthrough copy + scratch reset ----------------
__global__ void init_out_kernel(const float* __restrict__ md, const int* __restrict__ ni,
                                float* __restrict__ out, int N) {
    int i = blockIdx.x * blockDim.x + threadIdx.x;
    if (i < N) {
        out[i]     = md[i];
        out[N + i] = (float)ni[i];
    }
    if (i < NB) {
        g_best[i]  = 0xFFFFFFFFFFFFFFFFULL;
        g_fbest[i] = 0xFFFFFFFFFFFFFFFFULL;
        g_cnt[i]   = 0;
    }
    if (i == 0) g_qcnt = 0;
}

// ---------------- main: mma.sync bf16 GEMM (KC=64) + block-row min + candidates ----------------
__global__ __launch_bounds__(256, 2)
void gemm_min_kernel() {
    extern __shared__ char smem[];
    const uint32_t sb = smem_u32(smem);
    const int t   = threadIdx.x;
    const int l   = t & 31;
    const int wid = t >> 5;
    const int wm  = wid >> 2;          // 0..1 : m block of 64
    const int wn  = wid & 3;           // 0..3 : n block of 32
    const int bm  = blockIdx.y * BM;
    const int bn  = blockIdx.x * BN;

    // cp.async assignment: thread handles one 64B half-row of A and B (4x16B each)
    const int r0 = t >> 1;             // 0..127
    const int h  = t & 1;              // which 64B half of the 128B row
    const uint32_t swBase = (uint32_t)r0 * PITCH + (uint32_t)h * 64;
    const uint32_t gBase  = (uint32_t)r0 * D_DIM + (uint32_t)h * 32;

    const __nv_bfloat16* A0 = g_xb + (size_t)bm * D_DIM;
    const __nv_bfloat16* B0 = g_yb + (size_t)bn * D_DIM;

    auto load_chunk = [&](int c) {
        const __nv_bfloat16* A = A0 + c * KC;
        const __nv_bfloat16* B = B0 + c * KC;
        uint32_t stage = sb + (uint32_t)(c % STAGES) * STAGE_BYTES;
        #pragma unroll
        for (int s = 0; s < 4; s++) {
            cp_async16(stage + swBase + s * 16,         A + gBase + s * 8);
            cp_async16(stage + ATILE + swBase + s * 16, B + gBase + s * 8);
        }
        asm volatile("cp.async.commit_group;\n" ::: "memory");
    };

    load_chunk(0);
    load_chunk(1);

    const uint32_t aLane = (uint32_t)(wm * 64 + (l & 15)) * PITCH + (uint32_t)(l >> 4) * 16;
    const uint32_t bLane = (uint32_t)(wn * 32 + ((l >> 4) << 3) + (l & 7)) * PITCH +
                           (uint32_t)(((l >> 3) & 1) * 16) + ATILE;

    float acc[4][4][4];
    #pragma unroll
    for (int i = 0; i < 4; i++)
        #pragma unroll
        for (int j = 0; j < 4; j++)
            #pragma unroll
            for (int q = 0; q < 4; q++) acc[i][j][q] = 0.f;

    for (int c = 0; c < NCHUNK; c++) {
        if (c < NCHUNK - 1) asm volatile("cp.async.wait_group 1;\n" ::: "memory");
        else                asm volatile("cp.async.wait_group 0;\n" ::: "memory");
        __syncthreads();
        if (c <= NCHUNK - 3) load_chunk(c + 2);

        const uint32_t stage = sb + (uint32_t)(c % STAGES) * STAGE_BYTES;
        #pragma unroll
        for (int ks = 0; ks < 4; ks++) {           // 4 k16-steps per 64-wide chunk
            uint32_t a[4][4], b[2][4];
            #pragma unroll
            for (int i = 0; i < 4; i++)
                ldsm_x4(a[i][0], a[i][1], a[i][2], a[i][3],
                        stage + aLane + (uint32_t)i * 16 * PITCH + (uint32_t)ks * 32);
            #pragma unroll
            for (int jp = 0; jp < 2; jp++)
                ldsm_x4(b[jp][0], b[jp][1], b[jp][2], b[jp][3],
                        stage + bLane + (uint32_t)jp * 16 * PITCH + (uint32_t)ks * 32);
            #pragma unroll
            for (int i = 0; i < 4; i++) {
                #pragma unroll
                for (int jp = 0; jp < 2; jp++) {
                    mma16816(acc[i][jp * 2 + 0], a[i], &b[jp][0]);
                    mma16816(acc[i][jp * 2 + 1], a[i], &b[jp][2]);
                }
            }
        }
    }
    __syncthreads();

    // smem after mainloop: y2 staging + per-row block minima
    float* y2s = (float*)smem;
    unsigned long long* s_rmin = (unsigned long long*)(smem + 512);
    if (t < BN) y2s[t] = g_y2[bn + t];
    if (t < BM) s_rmin[t] = 0xFFFFFFFFFFFFFFFFULL;
    __syncthreads();

    // phase 1: acc -> v-hat (in place), warp-tile row min -> shared block-row min
    const int nbase = wn * 32 + 2 * (l & 3);
    #pragma unroll
    for (int i = 0; i < 4; i++) {
        const int rlA = wm * 64 + i * 16 + (l >> 2);
        float vA = 3.4e38f, vB = 3.4e38f;
        int   jA = 0,       jB = 0;
        #pragma unroll
        for (int j = 0; j < 4; j++) {
            int n0 = nbase + j * 8;
            float y20 = y2s[n0], y21 = y2s[n0 + 1];
            acc[i][j][0] = fmaf(-2.f, acc[i][j][0], y20);
            acc[i][j][1] = fmaf(-2.f, acc[i][j][1], y21);
            acc[i][j][2] = fmaf(-2.f, acc[i][j][2], y20);
            acc[i][j][3] = fmaf(-2.f, acc[i][j][3], y21);
            if (acc[i][j][0] < vA) { vA = acc[i][j][0]; jA = n0; }
            if (acc[i][j][1] < vA) { vA = acc[i][j][1]; jA = n0 + 1; }
            if (acc[i][j][2] < vB) { vB = acc[i][j][2]; jB = n0; }
            if (acc[i][j][3] < vB) { vB = acc[i][j][3]; jB = n0 + 1; }
        }
        unsigned long long keyA =
            ((unsigned long long)__float_as_uint(vA) << 32) | (unsigned)(bn + jA);
        unsigned long long keyB =
            ((unsigned long long)__float_as_uint(vB) << 32) | (unsigned)(bn + jB);
        #pragma unroll
        for (int o = 1; o < 4; o <<= 1) {
            unsigned long long oA = __shfl_xor_sync(0xffffffffu, keyA, o);
            unsigned long long oB = __shfl_xor_sync(0xffffffffu, keyB, o);
            if (oA < keyA) keyA = oA;
            if (oB < keyB) keyB = oB;
        }
        if ((l & 3) == 0) {
            atomicMin(&s_rmin[rlA],     keyA);
            atomicMin(&s_rmin[rlA + 8], keyB);
        }
    }
    __syncthreads();

    // phase 2: publish block min globally, fold old global in
    if (wn == 0 && (l & 3) == 0) {
        #pragma unroll
        for (int i = 0; i < 4; i++) {
            int rlA = wm * 64 + i * 16 + (l >> 2);
            unsigned long long kA = s_rmin[rlA];
            unsigned long long oA = atomicMin(&g_best[bm + rlA], kA);
            if (oA < kA) s_rmin[rlA] = oA;
            int rlB = rlA + 8;
            unsigned long long kB = s_rmin[rlB];
            unsigned long long oB = atomicMin(&g_best[bm + rlB], kB);
            if (oB < kB) s_rmin[rlB] = oB;
        }
    }
    __syncthreads();

    // phase 3: append candidates within (running min + MARGIN)
    #pragma unroll
    for (int i = 0; i < 4; i++) {
        const int rlA = wm * 64 + i * 16 + (l >> 2);
        const int rA = bm + rlA;
        const int rB = rA + 8;
        const float tA = __uint_as_float((unsigned)(s_rmin[rlA] >> 32))     + MARGIN;
        const float tB = __uint_as_float((unsigned)(s_rmin[rlA + 8] >> 32)) + MARGIN;
        #pragma unroll
        for (int j = 0; j < 4; j++) {
            #pragma unroll
            for (int q = 0; q < 2; q++) {
                int col = bn + nbase + j * 8 + q;
                float va = acc[i][j][q];
                if (va <= tA) {
                    int p = atomicAdd(&g_cnt[rA], 1);
                    if (p < CAP)
                        g_cand[(size_t)rA * CAP + p] =
                            ((unsigned long long)__float_as_uint(va) << 32) | (unsigned)col;
                }
                float vb = acc[i][j][2 + q];
                if (vb <= tB) {
                    int p = atomicAdd(&g_cnt[rB], 1);
                    if (p < CAP)
                        g_cand[(size_t)rB * CAP + p] =
                            ((unsigned long long)__float_as_uint(vb) << 32) | (unsigned)col;
                }
            }
        }
    }
}

// ---------------- filter: per-row window -> global work queue (plain atomics) ----------------
__global__ __launch_bounds__(128)
void filter_kernel() {
    const int row = blockIdx.x * 4 + (threadIdx.x >> 5);   // one warp per row
    const int l   = threadIdx.x & 31;
    const float thresh = __uint_as_float((unsigned)(g_best[row] >> 32)) + MARGIN;
    const int cnt = min(g_cnt[row], CAP);
    for (int c = l; c < cnt; c += 32) {
        unsigned long long e = g_cand[(size_t)row * CAP + c];
        if (__uint_as_float((unsigned)(e >> 32)) <= thresh) {
            int col = (int)(unsigned)(e & 0xffffffffULL);
            int pos = atomicAdd(&g_qcnt, 1);
            if (pos < QCAP) g_q[pos] = ((unsigned)row << 12) | (unsigned)col;
        }
    }
}

// ---------------- dot: one warp per queue entry, fp32 FFMA (R1/R12-validated numerics) ----------------
__global__ __launch_bounds__(256)
void dot_kernel(const float* __restrict__ x, const float* __restrict__ y) {
    const int gw = (blockIdx.x * 256 + threadIdx.x) >> 5;
    const int l  = threadIdx.x & 31;
    const int nwarps = gridDim.x * 8;
    const int nq = min(g_qcnt, QCAP);
    for (int q = gw; q < nq; q += nwarps) {
        const unsigned e = g_q[q];
        const int row = (int)(e >> 12);
        const int col = (int)(e & 4095u);
        const float* xr = x + (size_t)row * D_DIM;
        const float* yr = y + (size_t)col * D_DIM;
        float s0 = 0.f, s1 = 0.f, s2 = 0.f, s3 = 0.f;
        #pragma unroll 4
        for (int k = l * 4; k < D_DIM; k += 32 * 4) {
            float4 xv = *(const float4*)(xr + k);
            float4 yv = *(const float4*)(yr + k);
            s0 = fmaf(xv.x, yv.x, s0);
            s1 = fmaf(xv.y, yv.y, s1);
            s2 = fmaf(xv.z, yv.z, s2);
            s3 = fmaf(xv.w, yv.w, s3);
        }
        float s = (s0 + s1) + (s2 + s3);
        #pragma unroll
        for (int o = 16; o > 0; o >>= 1) s += __shfl_xor_sync(0xffffffffu, s, o);
        if (l == 0) {
            float v = fmaf(-2.f, s, g_y2[col]);
            unsigned long long k =
                ((unsigned long long)__float_as_uint(v) << 32) | (unsigned)col;
            atomicMin(&g_fbest[row], k);
        }
    }
}

// ---------------- finalize ----------------
__global__ void final_kernel(const float* __restrict__ md, float* __restrict__ out,
                             int N, const int* __restrict__ xs, const int* __restrict__ ys) {
    int i = blockIdx.x * blockDim.x + threadIdx.x;
    if (i >= NB) return;
    unsigned long long k = g_fbest[i];
    float v = __uint_as_float((unsigned)(k >> 32));
    int   j = (int)(unsigned)(k & 0xffffffffULL);
    float dist = sqrtf(fmaxf(g_x2[i] + v, 0.f));
    const int x0 = xs[0];
    const int y0 = ys[0];
    out[x0 + i]     = fminf(dist, md[x0 + i]);
    out[N + x0 + i] = (float)(j + y0);
}

// ---------------- launch ----------------
extern "C" void kernel_launch(void* const* d_in, const int* in_sizes, int n_in,
                              void* d_out, int out_size) {
    const float* x  = (const float*)d_in[0];
    const float* y  = (const float*)d_in[1];
    const float* md = (const float*)d_in[2];
    const int*   ni = (const int*)d_in[3];
    const int*   xs = (const int*)d_in[4];
    const int*   ys = (const int*)d_in[5];
    float* out = (float*)d_out;
    const int N = in_sizes[2];   // 50000

    cudaFuncSetAttribute(gemm_min_kernel,
                         cudaFuncAttributeMaxDynamicSharedMemorySize, SMEM_TOTAL);

    convert_norms_kernel<<<2 * NB, 256>>>(x, y);
    init_out_kernel<<<(N + 255) / 256, 256>>>(md, ni, out, N);
    dim3 grid(NB / BN, NB / BM);
    gemm_min_kernel<<<grid, 256, SMEM_TOTAL>>>();
    filter_kernel<<<NB / 4, 128>>>();
    dot_kernel<<<1184, 256>>>(x, y);
    final_kernel<<<(NB + 255) / 256, 256>>>(md, out, N, xs, ys);
}

// round 15
// speedup vs baseline: 1.2158x; 1.2158x over previous
#include <cuda_runtime.h>
#include <cuda_bf16.h>
#include <stdint.h>

#define D_DIM 3072
#define NB    4096
#define BM    128
#define BN    128
#define KC    32
#define NCHUNK (D_DIM / KC)        // 96 (single bf16 pass)
#define STAGES 4
#define PITCH  80                  // bytes per smem row (32 bf16 = 64B + 16B pad)
#define ATILE  (BM * PITCH)        // 10240 bytes
#define STAGE_BYTES (2 * ATILE)    // A + B
#define SMEM_TOTAL (STAGES * STAGE_BYTES)   // 81920 (2 CTAs/SM)
#define MARGIN 48.0f               // >> 2*max|vhat-v|; validated R7/R9/R11/R12
#define CAP    512                 // per-row candidate slots
#define QCAP   (NB * 64)           // global queue capacity

// ---------------- scratch (no cudaMalloc allowed) ----------------
__device__ float g_x2[NB];
__device__ float g_y2[NB];
__device__ unsigned long long g_best[NB];    // approx: (vhat bits << 32) | col
__device__ unsigned long long g_fbest[NB];   // refined: (v bits << 32) | col
__device__ int g_cnt[NB];
__device__ int g_qcnt;
__device__ unsigned long long g_cand[(size_t)NB * CAP];
__device__ unsigned g_q[QCAP];               // packed (row << 12) | col
__device__ __nv_bfloat16 g_xb[(size_t)NB * D_DIM];
__device__ __nv_bfloat16 g_yb[(size_t)NB * D_DIM];

// ---------------- PTX helpers ----------------
__device__ __forceinline__ uint32_t smem_u32(const void* p) {
    uint32_t a;
    asm("{ .reg .u64 t; cvta.to.shared.u64 t, %1; cvt.u32.u64 %0, t; }" : "=r"(a) : "l"(p));
    return a;
}
__device__ __forceinline__ void cp_async16(uint32_t s, const void* g) {
    asm volatile("cp.async.cg.shared.global [%0], [%1], 16;\n" :: "r"(s), "l"(g) : "memory");
}
__device__ __forceinline__ void ldsm_x4(uint32_t& r0, uint32_t& r1, uint32_t& r2, uint32_t& r3,
                                        uint32_t addr) {
    asm volatile("ldmatrix.sync.aligned.m8n8.x4.shared.b16 {%0,%1,%2,%3}, [%4];"
                 : "=r"(r0), "=r"(r1), "=r"(r2), "=r"(r3) : "r"(addr));
}
__device__ __forceinline__ void mma16816(float* d, const uint32_t* a, const uint32_t* b) {
    asm volatile(
        "mma.sync.aligned.m16n8k16.row.col.f32.bf16.bf16.f32 "
        "{%0,%1,%2,%3}, {%4,%5,%6,%7}, {%8,%9}, {%0,%1,%2,%3};"
        : "+f"(d[0]), "+f"(d[1]), "+f"(d[2]), "+f"(d[3])
        : "r"(a[0]), "r"(a[1]), "r"(a[2]), "r"(a[3]), "r"(b[0]), "r"(b[1]));
}

// ---------------- fused fp32->bf16 conversion + row squared-norms ----------------
__global__ void convert_norms_kernel(const float* __restrict__ x, const float* __restrict__ y) {
    const int row = blockIdx.x;
    const bool isY = row >= NB;
    const int r = isY ? row - NB : row;
    const float* src = (isY ? y : x) + (size_t)r * D_DIM;
    __nv_bfloat16* dst = (isY ? g_yb : g_xb) + (size_t)r * D_DIM;

    float s = 0.f;
    #pragma unroll 3
    for (int k = threadIdx.x * 4; k < D_DIM; k += 256 * 4) {
        float4 v = *(const float4*)(src + k);
        s += v.x * v.x + v.y * v.y + v.z * v.z + v.w * v.w;
        __nv_bfloat162 p0 = __halves2bfloat162(__float2bfloat16(v.x), __float2bfloat16(v.y));
        __nv_bfloat162 p1 = __halves2bfloat162(__float2bfloat16(v.z), __float2bfloat16(v.w));
        ((__nv_bfloat162*)(dst + k))[0] = p0;
        ((__nv_bfloat162*)(dst + k))[1] = p1;
    }
    __shared__ float sm[256];
    sm[threadIdx.x] = s;
    __syncthreads();
    for (int o = 128; o > 0; o >>= 1) {
        if (threadIdx.x < o) sm[threadIdx.x] += sm[threadIdx.x + o];
        __syncthreads();
    }
    if (threadIdx.x == 0) {
        if (isY) g_y2[r] = sm[0];
        else     g_x2[r] = sm[0];
    }
}

// ---------------- passthrough copy + scratch reset ----------------
__global__ void init_out_kernel(const float* __restrict__ md, const int* __restrict__ ni,
                                float* __restrict__ out, int N) {
    int i = blockIdx.x * blockDim.x + threadIdx.x;
    if (i < N) {
        out[i]     = md[i];
        out[N + i] = (float)ni[i];
    }
    if (i < NB) {
        g_best[i]  = 0xFFFFFFFFFFFFFFFFULL;
        g_fbest[i] = 0xFFFFFFFFFFFFFFFFULL;
        g_cnt[i]   = 0;
    }
    if (i == 0) g_qcnt = 0;
}

// ---------------- main: mma.sync bf16 GEMM + block-row min + candidate collection ----------------
__global__ __launch_bounds__(256, 2)
void gemm_min_kernel() {
    extern __shared__ char smem[];
    const uint32_t sb = smem_u32(smem);
    const int t   = threadIdx.x;
    const int l   = t & 31;
    const int wid = t >> 5;
    const int wm  = wid >> 2;          // 0..1 : m block of 64
    const int wn  = wid & 3;           // 0..3 : n block of 32
    const int bm  = blockIdx.y * BM;
    const int bn  = blockIdx.x * BN;

    const int r0  = t >> 2;
    const int c16 = t & 3;
    const uint32_t swOff0 = (uint32_t)r0 * PITCH + (uint32_t)c16 * 16;
    const uint32_t swOff1 = (uint32_t)(r0 + 64) * PITCH + (uint32_t)c16 * 16;
    const uint32_t gOff0  = (uint32_t)r0 * D_DIM + (uint32_t)c16 * 8;
    const uint32_t gOff1  = (uint32_t)(r0 + 64) * D_DIM + (uint32_t)c16 * 8;

    const __nv_bfloat16* A0 = g_xb + (size_t)bm * D_DIM;
    const __nv_bfloat16* B0 = g_yb + (size_t)bn * D_DIM;

    auto load_chunk = [&](int c) {
        const __nv_bfloat16* A = A0 + c * KC;
        const __nv_bfloat16* B = B0 + c * KC;
        uint32_t stage = sb + (uint32_t)(c % STAGES) * STAGE_BYTES;
        cp_async16(stage + swOff0,         A + gOff0);
        cp_async16(stage + swOff1,         A + gOff1);
        cp_async16(stage + ATILE + swOff0, B + gOff0);
        cp_async16(stage + ATILE + swOff1, B + gOff1);
        asm volatile("cp.async.commit_group;\n" ::: "memory");
    };

    load_chunk(0);
    load_chunk(1);
    load_chunk(2);

    const uint32_t aLane = (uint32_t)(wm * 64 + (l & 15)) * PITCH + (uint32_t)(l >> 4) * 16;
    const uint32_t bLane = (uint32_t)(wn * 32 + ((l >> 4) << 3) + (l & 7)) * PITCH +
                           (uint32_t)(((l >> 3) & 1) * 16) + ATILE;

    float acc[4][4][4];
    #pragma unroll
    for (int i = 0; i < 4; i++)
        #pragma unroll
        for (int j = 0; j < 4; j++)
            #pragma unroll
            for (int q = 0; q < 4; q++) acc[i][j][q] = 0.f;

    for (int c = 0; c < NCHUNK; c++) {
        // wait until chunk c's group is complete, given how many groups are in flight
        if (c <= NCHUNK - 3)      asm volatile("cp.async.wait_group 2;\n" ::: "memory");
        else if (c == NCHUNK - 2) asm volatile("cp.async.wait_group 1;\n" ::: "memory");
        else                      asm volatile("cp.async.wait_group 0;\n" ::: "memory");
        __syncthreads();
        if (c <= NCHUNK - 4) load_chunk(c + 3);

        const uint32_t stage = sb + (uint32_t)(c % STAGES) * STAGE_BYTES;
        #pragma unroll
        for (int ks = 0; ks < 2; ks++) {
            uint32_t a[4][4], b[2][4];
            #pragma unroll
            for (int i = 0; i < 4; i++)
                ldsm_x4(a[i][0], a[i][1], a[i][2], a[i][3],
                        stage + aLane + (uint32_t)i * 16 * PITCH + (uint32_t)ks * 32);
            #pragma unroll
            for (int jp = 0; jp < 2; jp++)
                ldsm_x4(b[jp][0], b[jp][1], b[jp][2], b[jp][3],
                        stage + bLane + (uint32_t)jp * 16 * PITCH + (uint32_t)ks * 32);
            #pragma unroll
            for (int i = 0; i < 4; i++) {
                #pragma unroll
                for (int jp = 0; jp < 2; jp++) {
                    mma16816(acc[i][jp * 2 + 0], a[i], &b[jp][0]);
                    mma16816(acc[i][jp * 2 + 1], a[i], &b[jp][2]);
                }
            }
        }
    }
    __syncthreads();

    // smem after mainloop: y2 staging + per-row block minima
    float* y2s = (float*)smem;
    unsigned long long* s_rmin = (unsigned long long*)(smem + 512);
    if (t < BN) y2s[t] = g_y2[bn + t];
    if (t < BM) s_rmin[t] = 0xFFFFFFFFFFFFFFFFULL;
    __syncthreads();

    // phase 1: acc -> v-hat (in place), warp-tile row min -> shared block-row min
    const int nbase = wn * 32 + 2 * (l & 3);
    #pragma unroll
    for (int i = 0; i < 4; i++) {
        const int rlA = wm * 64 + i * 16 + (l >> 2);
        float vA = 3.4e38f, vB = 3.4e38f;
        int   jA = 0,       jB = 0;
        #pragma unroll
        for (int j = 0; j < 4; j++) {
            int n0 = nbase + j * 8;
            float y20 = y2s[n0], y21 = y2s[n0 + 1];
            acc[i][j][0] = fmaf(-2.f, acc[i][j][0], y20);
            acc[i][j][1] = fmaf(-2.f, acc[i][j][1], y21);
            acc[i][j][2] = fmaf(-2.f, acc[i][j][2], y20);
            acc[i][j][3] = fmaf(-2.f, acc[i][j][3], y21);
            if (acc[i][j][0] < vA) { vA = acc[i][j][0]; jA = n0; }
            if (acc[i][j][1] < vA) { vA = acc[i][j][1]; jA = n0 + 1; }
            if (acc[i][j][2] < vB) { vB = acc[i][j][2]; jB = n0; }
            if (acc[i][j][3] < vB) { vB = acc[i][j][3]; jB = n0 + 1; }
        }
        unsigned long long keyA =
            ((unsigned long long)__float_as_uint(vA) << 32) | (unsigned)(bn + jA);
        unsigned long long keyB =
            ((unsigned long long)__float_as_uint(vB) << 32) | (unsigned)(bn + jB);
        #pragma unroll
        for (int o = 1; o < 4; o <<= 1) {
            unsigned long long oA = __shfl_xor_sync(0xffffffffu, keyA, o);
            unsigned long long oB = __shfl_xor_sync(0xffffffffu, keyB, o);
            if (oA < keyA) keyA = oA;
            if (oB < keyB) keyB = oB;
        }
        if ((l & 3) == 0) {
            atomicMin(&s_rmin[rlA],     keyA);
            atomicMin(&s_rmin[rlA + 8], keyB);
        }
    }
    __syncthreads();

    // phase 2: publish block min globally, fold old global in
    if (wn == 0 && (l & 3) == 0) {
        #pragma unroll
        for (int i = 0; i < 4; i++) {
            int rlA = wm * 64 + i * 16 + (l >> 2);
            unsigned long long kA = s_rmin[rlA];
            unsigned long long oA = atomicMin(&g_best[bm + rlA], kA);
            if (oA < kA) s_rmin[rlA] = oA;
            int rlB = rlA + 8;
            unsigned long long kB = s_rmin[rlB];
            unsigned long long oB = atomicMin(&g_best[bm + rlB], kB);
            if (oB < kB) s_rmin[rlB] = oB;
        }
    }
    __syncthreads();

    // phase 3: append candidates within (running min + MARGIN)
    #pragma unroll
    for (int i = 0; i < 4; i++) {
        const int rlA = wm * 64 + i * 16 + (l >> 2);
        const int rA = bm + rlA;
        const int rB = rA + 8;
        const float tA = __uint_as_float((unsigned)(s_rmin[rlA] >> 32))     + MARGIN;
        const float tB = __uint_as_float((unsigned)(s_rmin[rlA + 8] >> 32)) + MARGIN;
        #pragma unroll
        for (int j = 0; j < 4; j++) {
            #pragma unroll
            for (int q = 0; q < 2; q++) {
                int col = bn + nbase + j * 8 + q;
                float va = acc[i][j][q];
                if (va <= tA) {
                    int p = atomicAdd(&g_cnt[rA], 1);
                    if (p < CAP)
                        g_cand[(size_t)rA * CAP + p] =
                            ((unsigned long long)__float_as_uint(va) << 32) | (unsigned)col;
                }
                float vb = acc[i][j][2 + q];
                if (vb <= tB) {
                    int p = atomicAdd(&g_cnt[rB], 1);
                    if (p < CAP)
                        g_cand[(size_t)rB * CAP + p] =
                            ((unsigned long long)__float_as_uint(vb) << 32) | (unsigned)col;
                }
            }
        }
    }
}

// ---------------- filter: per-row window -> global work queue (plain atomics) ----------------
__global__ __launch_bounds__(128)
void filter_kernel() {
    const int row = blockIdx.x * 4 + (threadIdx.x >> 5);   // one warp per row
    const int l   = threadIdx.x & 31;
    const float thresh = __uint_as_float((unsigned)(g_best[row] >> 32)) + MARGIN;
    const int cnt = min(g_cnt[row], CAP);
    for (int c = l; c < cnt; c += 32) {
        unsigned long long e = g_cand[(size_t)row * CAP + c];
        if (__uint_as_float((unsigned)(e >> 32)) <= thresh) {
            int col = (int)(unsigned)(e & 0xffffffffULL);
            int pos = atomicAdd(&g_qcnt, 1);
            if (pos < QCAP) g_q[pos] = ((unsigned)row << 12) | (unsigned)col;
        }
    }
}

// ---------------- dot: one warp per queue entry, fp32 FFMA (R1/R12-validated numerics) ----------------
__global__ __launch_bounds__(256)
void dot_kernel(const float* __restrict__ x, const float* __restrict__ y) {
    const int gw = (blockIdx.x * 256 + threadIdx.x) >> 5;
    const int l  = threadIdx.x & 31;
    const int nwarps = gridDim.x * 8;
    const int nq = min(g_qcnt, QCAP);
    for (int q = gw; q < nq; q += nwarps) {
        const unsigned e = g_q[q];
        const int row = (int)(e >> 12);
        const int col = (int)(e & 4095u);
        const float* xr = x + (size_t)row * D_DIM;
        const float* yr = y + (size_t)col * D_DIM;
        float s0 = 0.f, s1 = 0.f, s2 = 0.f, s3 = 0.f;
        #pragma unroll 4
        for (int k = l * 4; k < D_DIM; k += 32 * 4) {
            float4 xv = *(const float4*)(xr + k);
            float4 yv = *(const float4*)(yr + k);
            s0 = fmaf(xv.x, yv.x, s0);
            s1 = fmaf(xv.y, yv.y, s1);
            s2 = fmaf(xv.z, yv.z, s2);
            s3 = fmaf(xv.w, yv.w, s3);
        }
        float s = (s0 + s1) + (s2 + s3);
        #pragma unroll
        for (int o = 16; o > 0; o >>= 1) s += __shfl_xor_sync(0xffffffffu, s, o);
        if (l == 0) {
            float v = fmaf(-2.f, s, g_y2[col]);
            unsigned long long k =
                ((unsigned long long)__float_as_uint(v) << 32) | (unsigned)col;
            atomicMin(&g_fbest[row], k);
        }
    }
}

// ---------------- finalize ----------------
__global__ void final_kernel(const float* __restrict__ md, float* __restrict__ out,
                             int N, const int* __restrict__ xs, const int* __restrict__ ys) {
    int i = blockIdx.x * blockDim.x + threadIdx.x;
    if (i >= NB) return;
    unsigned long long k = g_fbest[i];
    float v = __uint_as_float((unsigned)(k >> 32));
    int   j = (int)(unsigned)(k & 0xffffffffULL);
    float dist = sqrtf(fmaxf(g_x2[i] + v, 0.f));
    const int x0 = xs[0];
    const int y0 = ys[0];
    out[x0 + i]     = fminf(dist, md[x0 + i]);
    out[N + x0 + i] = (float)(j + y0);
}

// ---------------- launch ----------------
extern "C" void kernel_launch(void* const* d_in, const int* in_sizes, int n_in,
                              void* d_out, int out_size) {
    const float* x  = (const float*)d_in[0];
    const float* y  = (const float*)d_in[1];
    const float* md = (const float*)d_in[2];
    const int*   ni = (const int*)d_in[3];
    const int*   xs = (const int*)d_in[4];
    const int*   ys = (const int*)d_in[5];
    float* out = (float*)d_out;
    const int N = in_sizes[2];   // 50000

    cudaFuncSetAttribute(gemm_min_kernel,
                         cudaFuncAttributeMaxDynamicSharedMemorySize, SMEM_TOTAL);

    convert_norms_kernel<<<2 * NB, 256>>>(x, y);
    init_out_kernel<<<(N + 255) / 256, 256>>>(md, ni, out, N);
    dim3 grid(NB / BN, NB / BM);
    gemm_min_kernel<<<grid, 256, SMEM_TOTAL>>>();
    filter_kernel<<<NB / 4, 128>>>();
    dot_kernel<<<1184, 256>>>(x, y);
    final_kernel<<<(NB + 255) / 256, 256>>>(md, out, N, xs, ys);
}

// round 16
// speedup vs baseline: 1.2914x; 1.0622x over previous
#include <cuda_runtime.h>
#include <cuda_bf16.h>
#include <stdint.h>

#define D_DIM 3072
#define NB    4096
#define BM    128
#define BN    128
#define KC    32
#define NCHUNK (D_DIM / KC)        // 96 (single bf16 pass)
#define STAGES 3
#define PITCH  80                  // bytes per smem row (32 bf16 = 64B + 16B pad)
#define ATILE  (BM * PITCH)        // 10240 bytes
#define STAGE_BYTES (2 * ATILE)    // A + B
#define SMEM_TOTAL (STAGES * STAGE_BYTES)   // 61440
#define MARGIN 48.0f               // >> 2*max|vhat-v|; validated R7/R9/R11/R12
#define CAP    512                 // per-row candidate slots
#define QCAP   (NB * 64)           // global queue capacity

// ---------------- scratch (no cudaMalloc allowed) ----------------
__device__ float g_x2[NB];
__device__ float g_y2[NB];
__device__ unsigned long long g_best[NB];    // approx: (vhat bits << 32) | col
__device__ unsigned long long g_fbest[NB];   // refined: (v bits << 32) | col
__device__ int g_cnt[NB];
__device__ int g_qcnt;
__device__ unsigned long long g_cand[(size_t)NB * CAP];
__device__ unsigned g_q[QCAP];               // packed (row << 12) | col
__device__ __nv_bfloat16 g_xb[(size_t)NB * D_DIM];
__device__ __nv_bfloat16 g_yb[(size_t)NB * D_DIM];

// ---------------- PTX helpers ----------------
__device__ __forceinline__ uint32_t smem_u32(const void* p) {
    uint32_t a;
    asm("{ .reg .u64 t; cvta.to.shared.u64 t, %1; cvt.u32.u64 %0, t; }" : "=r"(a) : "l"(p));
    return a;
}
__device__ __forceinline__ void cp_async16(uint32_t s, const void* g) {
    asm volatile("cp.async.cg.shared.global [%0], [%1], 16;\n" :: "r"(s), "l"(g) : "memory");
}
__device__ __forceinline__ void ldsm_x4(uint32_t& r0, uint32_t& r1, uint32_t& r2, uint32_t& r3,
                                        uint32_t addr) {
    asm volatile("ldmatrix.sync.aligned.m8n8.x4.shared.b16 {%0,%1,%2,%3}, [%4];"
                 : "=r"(r0), "=r"(r1), "=r"(r2), "=r"(r3) : "r"(addr));
}
__device__ __forceinline__ void mma16816(float* d, const uint32_t* a, const uint32_t* b) {
    asm volatile(
        "mma.sync.aligned.m16n8k16.row.col.f32.bf16.bf16.f32 "
        "{%0,%1,%2,%3}, {%4,%5,%6,%7}, {%8,%9}, {%0,%1,%2,%3};"
        : "+f"(d[0]), "+f"(d[1]), "+f"(d[2]), "+f"(d[3])
        : "r"(a[0]), "r"(a[1]), "r"(a[2]), "r"(a[3]), "r"(b[0]), "r"(b[1]));
}

// ---------------- fused fp32->bf16 conversion + row norms: one warp per row ----------------
__global__ __launch_bounds__(256)
void convert_norms_kernel(const float* __restrict__ x, const float* __restrict__ y) {
    const int row = blockIdx.x * 8 + (threadIdx.x >> 5);   // 1024 blocks x 8 warps
    const int l   = threadIdx.x & 31;
    const bool isY = row >= NB;
    const int r = isY ? row - NB : row;
    const float* src = (isY ? y : x) + (size_t)r * D_DIM;
    __nv_bfloat16* dst = (isY ? g_yb : g_xb) + (size_t)r * D_DIM;

    float s = 0.f;
    #pragma unroll 6
    for (int k = l * 4; k < D_DIM; k += 32 * 4) {
        float4 v = *(const float4*)(src + k);
        s = fmaf(v.x, v.x, s);
        s = fmaf(v.y, v.y, s);
        s = fmaf(v.z, v.z, s);
        s = fmaf(v.w, v.w, s);
        __nv_bfloat162 p0 = __halves2bfloat162(__float2bfloat16(v.x), __float2bfloat16(v.y));
        __nv_bfloat162 p1 = __halves2bfloat162(__float2bfloat16(v.z), __float2bfloat16(v.w));
        ((__nv_bfloat162*)(dst + k))[0] = p0;
        ((__nv_bfloat162*)(dst + k))[1] = p1;
    }
    #pragma unroll
    for (int o = 16; o > 0; o >>= 1) s += __shfl_xor_sync(0xffffffffu, s, o);
    if (l == 0) {
        if (isY) g_y2[r] = s;
        else     g_x2[r] = s;
    }
}

// ---------------- passthrough copy + scratch reset ----------------
__global__ void init_out_kernel(const float* __restrict__ md, const int* __restrict__ ni,
                                float* __restrict__ out, int N) {
    int i = blockIdx.x * blockDim.x + threadIdx.x;
    if (i < N) {
        out[i]     = md[i];
        out[N + i] = (float)ni[i];
    }
    if (i < NB) {
        g_best[i]  = 0xFFFFFFFFFFFFFFFFULL;
        g_fbest[i] = 0xFFFFFFFFFFFFFFFFULL;
        g_cnt[i]   = 0;
    }
    if (i == 0) g_qcnt = 0;
}

// ---------------- main: mma.sync bf16 GEMM + block-row min + candidate collection ----------------
__global__ __launch_bounds__(256, 2)
void gemm_min_kernel() {
    extern __shared__ char smem[];
    const uint32_t sb = smem_u32(smem);
    const int t   = threadIdx.x;
    const int l   = t & 31;
    const int wid = t >> 5;
    const int wm  = wid >> 2;          // 0..1 : m block of 64
    const int wn  = wid & 3;           // 0..3 : n block of 32
    const int bm  = blockIdx.y * BM;
    const int bn  = blockIdx.x * BN;

    const int r0  = t >> 2;
    const int c16 = t & 3;
    const uint32_t swOff0 = (uint32_t)r0 * PITCH + (uint32_t)c16 * 16;
    const uint32_t swOff1 = (uint32_t)(r0 + 64) * PITCH + (uint32_t)c16 * 16;
    const uint32_t gOff0  = (uint32_t)r0 * D_DIM + (uint32_t)c16 * 8;
    const uint32_t gOff1  = (uint32_t)(r0 + 64) * D_DIM + (uint32_t)c16 * 8;

    const __nv_bfloat16* A0 = g_xb + (size_t)bm * D_DIM;
    const __nv_bfloat16* B0 = g_yb + (size_t)bn * D_DIM;

    auto load_chunk = [&](int c) {
        const __nv_bfloat16* A = A0 + c * KC;
        const __nv_bfloat16* B = B0 + c * KC;
        uint32_t stage = sb + (uint32_t)(c % STAGES) * STAGE_BYTES;
        cp_async16(stage + swOff0,         A + gOff0);
        cp_async16(stage + swOff1,         A + gOff1);
        cp_async16(stage + ATILE + swOff0, B + gOff0);
        cp_async16(stage + ATILE + swOff1, B + gOff1);
        asm volatile("cp.async.commit_group;\n" ::: "memory");
    };

    load_chunk(0);
    load_chunk(1);

    const uint32_t aLane = (uint32_t)(wm * 64 + (l & 15)) * PITCH + (uint32_t)(l >> 4) * 16;
    const uint32_t bLane = (uint32_t)(wn * 32 + ((l >> 4) << 3) + (l & 7)) * PITCH +
                           (uint32_t)(((l >> 3) & 1) * 16) + ATILE;

    float acc[4][4][4];
    #pragma unroll
    for (int i = 0; i < 4; i++)
        #pragma unroll
        for (int j = 0; j < 4; j++)
            #pragma unroll
            for (int q = 0; q < 4; q++) acc[i][j][q] = 0.f;

    for (int c = 0; c < NCHUNK; c++) {
        if (c < NCHUNK - 1) asm volatile("cp.async.wait_group 1;\n" ::: "memory");
        else                asm volatile("cp.async.wait_group 0;\n" ::: "memory");
        __syncthreads();
        if (c <= NCHUNK - 3) load_chunk(c + 2);

        const uint32_t stage = sb + (uint32_t)(c % STAGES) * STAGE_BYTES;
        #pragma unroll
        for (int ks = 0; ks < 2; ks++) {
            uint32_t a[4][4], b[2][4];
            #pragma unroll
            for (int i = 0; i < 4; i++)
                ldsm_x4(a[i][0], a[i][1], a[i][2], a[i][3],
                        stage + aLane + (uint32_t)i * 16 * PITCH + (uint32_t)ks * 32);
            #pragma unroll
            for (int jp = 0; jp < 2; jp++)
                ldsm_x4(b[jp][0], b[jp][1], b[jp][2], b[jp][3],
                        stage + bLane + (uint32_t)jp * 16 * PITCH + (uint32_t)ks * 32);
            #pragma unroll
            for (int i = 0; i < 4; i++) {
                #pragma unroll
                for (int jp = 0; jp < 2; jp++) {
                    mma16816(acc[i][jp * 2 + 0], a[i], &b[jp][0]);
                    mma16816(acc[i][jp * 2 + 1], a[i], &b[jp][2]);
                }
            }
        }
    }
    __syncthreads();

    // smem after mainloop: y2 staging + per-row block minima
    float* y2s = (float*)smem;
    unsigned long long* s_rmin = (unsigned long long*)(smem + 512);
    if (t < BN) y2s[t] = g_y2[bn + t];
    if (t < BM) s_rmin[t] = 0xFFFFFFFFFFFFFFFFULL;
    __syncthreads();

    // phase 1: acc -> v-hat (in place), warp-tile row min -> shared block-row min
    const int nbase = wn * 32 + 2 * (l & 3);
    #pragma unroll
    for (int i = 0; i < 4; i++) {
        const int rlA = wm * 64 + i * 16 + (l >> 2);
        float vA = 3.4e38f, vB = 3.4e38f;
        int   jA = 0,       jB = 0;
        #pragma unroll
        for (int j = 0; j < 4; j++) {
            int n0 = nbase + j * 8;
            float y20 = y2s[n0], y21 = y2s[n0 + 1];
            acc[i][j][0] = fmaf(-2.f, acc[i][j][0], y20);
            acc[i][j][1] = fmaf(-2.f, acc[i][j][1], y21);
            acc[i][j][2] = fmaf(-2.f, acc[i][j][2], y20);
            acc[i][j][3] = fmaf(-2.f, acc[i][j][3], y21);
            if (acc[i][j][0] < vA) { vA = acc[i][j][0]; jA = n0; }
            if (acc[i][j][1] < vA) { vA = acc[i][j][1]; jA = n0 + 1; }
            if (acc[i][j][2] < vB) { vB = acc[i][j][2]; jB = n0; }
            if (acc[i][j][3] < vB) { vB = acc[i][j][3]; jB = n0 + 1; }
        }
        unsigned long long keyA =
            ((unsigned long long)__float_as_uint(vA) << 32) | (unsigned)(bn + jA);
        unsigned long long keyB =
            ((unsigned long long)__float_as_uint(vB) << 32) | (unsigned)(bn + jB);
        #pragma unroll
        for (int o = 1; o < 4; o <<= 1) {
            unsigned long long oA = __shfl_xor_sync(0xffffffffu, keyA, o);
            unsigned long long oB = __shfl_xor_sync(0xffffffffu, keyB, o);
            if (oA < keyA) keyA = oA;
            if (oB < keyB) keyB = oB;
        }
        if ((l & 3) == 0) {
            atomicMin(&s_rmin[rlA],     keyA);
            atomicMin(&s_rmin[rlA + 8], keyB);
        }
    }
    __syncthreads();

    // phase 2: publish block min globally, fold old global in
    if (wn == 0 && (l & 3) == 0) {
        #pragma unroll
        for (int i = 0; i < 4; i++) {
            int rlA = wm * 64 + i * 16 + (l >> 2);
            unsigned long long kA = s_rmin[rlA];
            unsigned long long oA = atomicMin(&g_best[bm + rlA], kA);
            if (oA < kA) s_rmin[rlA] = oA;
            int rlB = rlA + 8;
            unsigned long long kB = s_rmin[rlB];
            unsigned long long oB = atomicMin(&g_best[bm + rlB], kB);
            if (oB < kB) s_rmin[rlB] = oB;
        }
    }
    __syncthreads();

    // phase 3: append candidates within (running min + MARGIN)
    #pragma unroll
    for (int i = 0; i < 4; i++) {
        const int rlA = wm * 64 + i * 16 + (l >> 2);
        const int rA = bm + rlA;
        const int rB = rA + 8;
        const float tA = __uint_as_float((unsigned)(s_rmin[rlA] >> 32))     + MARGIN;
        const float tB = __uint_as_float((unsigned)(s_rmin[rlA + 8] >> 32)) + MARGIN;
        #pragma unroll
        for (int j = 0; j < 4; j++) {
            #pragma unroll
            for (int q = 0; q < 2; q++) {
                int col = bn + nbase + j * 8 + q;
                float va = acc[i][j][q];
                if (va <= tA) {
                    int p = atomicAdd(&g_cnt[rA], 1);
                    if (p < CAP)
                        g_cand[(size_t)rA * CAP + p] =
                            ((unsigned long long)__float_as_uint(va) << 32) | (unsigned)col;
                }
                float vb = acc[i][j][2 + q];
                if (vb <= tB) {
                    int p = atomicAdd(&g_cnt[rB], 1);
                    if (p < CAP)
                        g_cand[(size_t)rB * CAP + p] =
                            ((unsigned long long)__float_as_uint(vb) << 32) | (unsigned)col;
                }
            }
        }
    }
}

// ---------------- filter: per-row window -> global work queue (plain atomics) ----------------
__global__ __launch_bounds__(128)
void filter_kernel() {
    const int row = blockIdx.x * 4 + (threadIdx.x >> 5);   // one warp per row
    const int l   = threadIdx.x & 31;
    const float thresh = __uint_as_float((unsigned)(g_best[row] >> 32)) + MARGIN;
    const int cnt = min(g_cnt[row], CAP);
    for (int c = l; c < cnt; c += 32) {
        unsigned long long e = g_cand[(size_t)row * CAP + c];
        if (__uint_as_float((unsigned)(e >> 32)) <= thresh) {
            int col = (int)(unsigned)(e & 0xffffffffULL);
            int pos = atomicAdd(&g_qcnt, 1);
            if (pos < QCAP) g_q[pos] = ((unsigned)row << 12) | (unsigned)col;
        }
    }
}

// ---------------- dot: one warp per queue entry, fp32 FFMA (R1/R12-validated numerics) ----------------
__global__ __launch_bounds__(256)
void dot_kernel(const float* __restrict__ x, const float* __restrict__ y) {
    const int gw = (blockIdx.x * 256 + threadIdx.x) >> 5;
    const int l  = threadIdx.x & 31;
    const int nwarps = gridDim.x * 8;
    const int nq = min(g_qcnt, QCAP);
    for (int q = gw; q < nq; q += nwarps) {
        const unsigned e = g_q[q];
        const int row = (int)(e >> 12);
        const int col = (int)(e & 4095u);
        const float* xr = x + (size_t)row * D_DIM;
        const float* yr = y + (size_t)col * D_DIM;
        float s0 = 0.f, s1 = 0.f, s2 = 0.f, s3 = 0.f;
        #pragma unroll 4
        for (int k = l * 4; k < D_DIM; k += 32 * 4) {
            float4 xv = *(const float4*)(xr + k);
            float4 yv = *(const float4*)(yr + k);
            s0 = fmaf(xv.x, yv.x, s0);
            s1 = fmaf(xv.y, yv.y, s1);
            s2 = fmaf(xv.z, yv.z, s2);
            s3 = fmaf(xv.w, yv.w, s3);
        }
        float s = (s0 + s1) + (s2 + s3);
        #pragma unroll
        for (int o = 16; o > 0; o >>= 1) s += __shfl_xor_sync(0xffffffffu, s, o);
        if (l == 0) {
            float v = fmaf(-2.f, s, g_y2[col]);
            unsigned long long k =
                ((unsigned long long)__float_as_uint(v) << 32) | (unsigned)col;
            atomicMin(&g_fbest[row], k);
        }
    }
}

// ---------------- finalize ----------------
__global__ void final_kernel(const float* __restrict__ md, float* __restrict__ out,
                             int N, const int* __restrict__ xs, const int* __restrict__ ys) {
    int i = blockIdx.x * blockDim.x + threadIdx.x;
    if (i >= NB) return;
    unsigned long long k = g_fbest[i];
    float v = __uint_as_float((unsigned)(k >> 32));
    int   j = (int)(unsigned)(k & 0xffffffffULL);
    float dist = sqrtf(fmaxf(g_x2[i] + v, 0.f));
    const int x0 = xs[0];
    const int y0 = ys[0];
    out[x0 + i]     = fminf(dist, md[x0 + i]);
    out[N + x0 + i] = (float)(j + y0);
}

// ---------------- launch ----------------
extern "C" void kernel_launch(void* const* d_in, const int* in_sizes, int n_in,
                              void* d_out, int out_size) {
    const float* x  = (const float*)d_in[0];
    const float* y  = (const float*)d_in[1];
    const float* md = (const float*)d_in[2];
    const int*   ni = (const int*)d_in[3];
    const int*   xs = (const int*)d_in[4];
    const int*   ys = (const int*)d_in[5];
    float* out = (float*)d_out;
    const int N = in_sizes[2];   // 50000

    cudaFuncSetAttribute(gemm_min_kernel,
                         cudaFuncAttributeMaxDynamicSharedMemorySize, SMEM_TOTAL);

    convert_norms_kernel<<<2 * NB / 8, 256>>>(x, y);
    init_out_kernel<<<(N + 255) / 256, 256>>>(md, ni, out, N);
    dim3 grid(NB / BN, NB / BM);
    gemm_min_kernel<<<grid, 256, SMEM_TOTAL>>>();
    filter_kernel<<<NB / 4, 128>>>();
    dot_kernel<<<1184, 256>>>(x, y);
    final_kernel<<<(NB + 255) / 256, 256>>>(md, out, N, xs, ys);
}